// round 4
// baseline (speedup 1.0000x reference)
#include <cuda_runtime.h>
#include <cstdint>
#include <cstddef>

#define KDIM 4096
#define NDIM 11008
#define MMAX 8192
#define NGRP 32                 // KDIM/128 quant groups
#define BKG  64                 // k per mainloop iter
#define STAGES 4
#define AROW 80                 // padded smem row bytes (64 data + 16 pad)
#define AHI_OFF 0
#define ALO_OFF (64 * AROW)             // 5120
#define BB_OFF  (2 * 64 * AROW)         // 10240
#define STAGE_B (BB_OFF + 128 * AROW)   // 20480
#define SSC_OFF (STAGES * STAGE_B)      // 81920, 32*128 f32 = 16384
#define SXS_OFF (SSC_OFF + 16384)       // 98304, 64*32 f32 = 8192
#define SMEM_TOTAL (SXS_OFF + 8192)     // 106496

// Static device scratch (no dynamic allocation allowed)
__device__ int8_t g_Xhi[(size_t)MMAX * KDIM];
__device__ int8_t g_Xlo[(size_t)MMAX * KDIM];
__device__ float  g_sxc[(size_t)MMAX * NGRP];
__device__ int8_t g_W8[(size_t)NDIM * KDIM];   // (q - z), transposed [N, K]

// ---------------- helpers ----------------
__device__ __forceinline__ uint32_t smem_u32(const void* p) {
    uint32_t a;
    asm("{ .reg .u64 t; cvta.to.shared.u64 t, %1; cvt.u32.u64 %0, t; }" : "=r"(a) : "l"(p));
    return a;
}

__device__ __forceinline__ void cp16(uint32_t sdst, const void* gsrc) {
    asm volatile("cp.async.cg.shared.global [%0], [%1], 16;" :: "r"(sdst), "l"(gsrc));
}

__device__ __forceinline__ void ldm_x4(uint32_t* r, uint32_t addr) {
    asm volatile("ldmatrix.sync.aligned.m8n8.x4.shared.b16 {%0,%1,%2,%3}, [%4];"
                 : "=r"(r[0]), "=r"(r[1]), "=r"(r[2]), "=r"(r[3]) : "r"(addr));
}

__device__ __forceinline__ void mma_s8(int* c, const uint32_t* a, uint32_t b0, uint32_t b1) {
    asm volatile("mma.sync.aligned.m16n8k32.row.col.s32.s8.s8.s32 "
                 "{%0,%1,%2,%3}, {%4,%5,%6,%7}, {%8,%9}, {%0,%1,%2,%3};"
                 : "+r"(c[0]), "+r"(c[1]), "+r"(c[2]), "+r"(c[3])
                 : "r"(a[0]), "r"(a[1]), "r"(a[2]), "r"(a[3]), "r"(b0), "r"(b1));
}

// ---------------- Kernel 1: x -> (hi, lo) int8 + per-(m,group) scale ----------------
__global__ void __launch_bounds__(256)
quant_x_kernel(const float* __restrict__ x, int M) {
    const int gidx = blockIdx.x * 8 + (threadIdx.x >> 5);
    const int lane = threadIdx.x & 31;
    const int m = gidx >> 5;               // gidx / NGRP
    const int g = gidx & 31;
    if (m >= M) return;
    const size_t off = (size_t)m * KDIM + g * 128 + lane * 4;
    float4 v = *reinterpret_cast<const float4*>(x + off);
    float amax = fmaxf(fmaxf(fabsf(v.x), fabsf(v.y)), fmaxf(fabsf(v.z), fabsf(v.w)));
#pragma unroll
    for (int o = 16; o; o >>= 1) amax = fmaxf(amax, __shfl_xor_sync(~0u, amax, o));
    amax = fmaxf(amax, 1e-30f);
    const float sx  = amax * (1.f / 127.f);
    const float inv = 127.f / amax;
    char hi[4], lo[4];
    const float* pv = &v.x;
#pragma unroll
    for (int j = 0; j < 4; ++j) {
        float t = pv[j] * inv;
        float h = rintf(t);
        float l = rintf((t - h) * 254.f);
        l = fminf(fmaxf(l, -127.f), 127.f);
        hi[j] = (char)(int)h;
        lo[j] = (char)(int)l;
    }
    *reinterpret_cast<char4*>(g_Xhi + off) = make_char4(hi[0], hi[1], hi[2], hi[3]);
    *reinterpret_cast<char4*>(g_Xlo + off) = make_char4(lo[0], lo[1], lo[2], lo[3]);
    if (lane == 0) g_sxc[(size_t)m * NGRP + g] = sx * (1.f / 254.f);
}

// ---------------- Kernel 2: qweight -> W8[N][K] = (q - z) int8 ----------------
__global__ void __launch_bounds__(256)
dequant_w_kernel(const int* __restrict__ qweight, const int* __restrict__ qzeros) {
    __shared__ int8_t s[64][80];
    const int t  = threadIdx.x;
    const int n0 = blockIdx.x * 64;
    const int k0 = blockIdx.y * 64;
    const int g  = k0 >> 7;

    const int nl = t & 63;
    const int n  = n0 + nl;
    const int z  = (int)(((uint32_t)qzeros[(size_t)g * (NDIM / 8) + (n >> 3)] >> ((n & 7) * 4)) & 15u) + 1;

#pragma unroll
    for (int p = 0; p < 2; ++p) {
        const int kpl = (t >> 6) + 4 * p;                     // 0..7
        const uint32_t qw = (uint32_t)qweight[(size_t)(k0 / 8 + kpl) * NDIM + n];
        char vals[8];
#pragma unroll
        for (int j = 0; j < 8; ++j)
            vals[j] = (char)((int)((qw >> (4 * j)) & 15u) - z);
        *reinterpret_cast<uint2*>(&s[nl][kpl * 8]) = *reinterpret_cast<uint2*>(vals);
    }
    __syncthreads();

    const int rn = t >> 2, c = t & 3;
    uint4 v = *reinterpret_cast<const uint4*>(&s[rn][c * 16]);
    *reinterpret_cast<uint4*>(&g_W8[(size_t)(n0 + rn) * KDIM + k0 + c * 16]) = v;
}

// ---------------- Kernel 3: int8 two-level GEMM ----------------
// CTA tile 64(M) x 128(N), 8 warps (2m x 4n), warp tile 32x32, BK=64, 4 stages.
__global__ void __launch_bounds__(256)
gemm_s8_kernel(const float* __restrict__ scales, const float* __restrict__ bias,
               float* __restrict__ out) {
    extern __shared__ char dsm[];
    const uint32_t sbase = smem_u32(dsm);
    float* ssc = reinterpret_cast<float*>(dsm + SSC_OFF);   // [32][128] scales tile
    float* sxs = reinterpret_cast<float*>(dsm + SXS_OFF);   // [64][32]  x combined scales

    const int tid  = threadIdx.x;
    const int lane = tid & 31;
    const int wid  = tid >> 5;
    const int warp_m = wid & 1;        // 2 -> 32 rows each
    const int warp_n = wid >> 1;       // 4 -> 32 cols each

    // grouped rasterization along M for B reuse
    const int PN = gridDim.x, PM = gridDim.y;
    const int bid = blockIdx.y * PN + blockIdx.x;
    const int GM = 16;
    const int npg = GM * PN;
    const int fm  = (bid / npg) * GM;
    const int gsm = (PM - fm < GM) ? (PM - fm) : GM;
    const int pm  = fm + (bid % gsm);
    const int pn  = (bid % npg) / gsm;
    const int m0 = pm * 64;
    const int n0 = pn * 128;

    // load scale tiles into smem
    for (int i = tid; i < 32 * 128; i += 256)
        ssc[i] = scales[(size_t)(i >> 7) * NDIM + n0 + (i & 127)];
    for (int i = tid; i < 64 * 32; i += 256)
        sxs[i] = g_sxc[(size_t)(m0 + (i >> 5)) * NGRP + (i & 31)];

    const int row = tid >> 2, c4 = (tid & 3) * 16;

    int   acch[2][4][4], accl[2][4][4];
    float accf[2][4][4];
#pragma unroll
    for (int mi = 0; mi < 2; ++mi)
#pragma unroll
        for (int ni = 0; ni < 4; ++ni)
#pragma unroll
            for (int v = 0; v < 4; ++v) {
                acch[mi][ni][v] = 0; accl[mi][ni][v] = 0; accf[mi][ni][v] = 0.f;
            }

    // fragment smem coordinates
    const int a_row = warp_m * 32 + (lane & 7) + ((lane >> 3) & 1) * 8;
    const int a_kb  = (lane >> 4) * 16;
    const int b_row = warp_n * 32 + (lane & 7) + ((lane >> 4) & 1) * 8;
    const int b_kb  = ((lane >> 3) & 1) * 16;

    const int NIT = KDIM / BKG;    // 64

    // prologue: stages 0..2
#pragma unroll
    for (int s = 0; s < STAGES - 1; ++s) {
        const int k0 = s * BKG;
        const uint32_t sp = sbase + s * STAGE_B;
        cp16(sp + AHI_OFF + row * AROW + c4, g_Xhi + (size_t)(m0 + row) * KDIM + k0 + c4);
        cp16(sp + ALO_OFF + row * AROW + c4, g_Xlo + (size_t)(m0 + row) * KDIM + k0 + c4);
        cp16(sp + BB_OFF + row * AROW + c4,        g_W8 + (size_t)(n0 + row) * KDIM + k0 + c4);
        cp16(sp + BB_OFF + (row + 64) * AROW + c4, g_W8 + (size_t)(n0 + 64 + row) * KDIM + k0 + c4);
        asm volatile("cp.async.commit_group;" ::: "memory");
    }

#pragma unroll 1
    for (int it = 0; it < NIT; ++it) {
        asm volatile("cp.async.wait_group 2;" ::: "memory");
        __syncthreads();

        const int nk = it + STAGES - 1;
        if (nk < NIT) {
            const int k0 = nk * BKG;
            const uint32_t sp = sbase + (nk & (STAGES - 1)) * STAGE_B;
            cp16(sp + AHI_OFF + row * AROW + c4, g_Xhi + (size_t)(m0 + row) * KDIM + k0 + c4);
            cp16(sp + ALO_OFF + row * AROW + c4, g_Xlo + (size_t)(m0 + row) * KDIM + k0 + c4);
            cp16(sp + BB_OFF + row * AROW + c4,        g_W8 + (size_t)(n0 + row) * KDIM + k0 + c4);
            cp16(sp + BB_OFF + (row + 64) * AROW + c4, g_W8 + (size_t)(n0 + 64 + row) * KDIM + k0 + c4);
        }
        asm volatile("cp.async.commit_group;" ::: "memory");

        const uint32_t sp = sbase + (it & (STAGES - 1)) * STAGE_B;
#pragma unroll
        for (int ks = 0; ks < 2; ++ks) {
            const int kb = ks * 32;
            uint32_t Ah[2][4], Al[2][4], Bf[2][4];
#pragma unroll
            for (int mi = 0; mi < 2; ++mi) {
                ldm_x4(Ah[mi], sp + AHI_OFF + (uint32_t)((a_row + mi * 16) * AROW + kb + a_kb));
                ldm_x4(Al[mi], sp + ALO_OFF + (uint32_t)((a_row + mi * 16) * AROW + kb + a_kb));
            }
#pragma unroll
            for (int nj = 0; nj < 2; ++nj)
                ldm_x4(Bf[nj], sp + BB_OFF + (uint32_t)((b_row + nj * 16) * AROW + kb + b_kb));
#pragma unroll
            for (int mi = 0; mi < 2; ++mi)
#pragma unroll
                for (int nj = 0; nj < 2; ++nj) {
                    mma_s8(acch[mi][2 * nj],     Ah[mi], Bf[nj][0], Bf[nj][1]);
                    mma_s8(acch[mi][2 * nj + 1], Ah[mi], Bf[nj][2], Bf[nj][3]);
                    mma_s8(accl[mi][2 * nj],     Al[mi], Bf[nj][0], Bf[nj][1]);
                    mma_s8(accl[mi][2 * nj + 1], Al[mi], Bf[nj][2], Bf[nj][3]);
                }
        }

        if (it & 1) {       // group boundary (128 k consumed)
            const int g = it >> 1;
#pragma unroll
            for (int mi = 0; mi < 2; ++mi) {
                const int lm = warp_m * 32 + mi * 16 + (lane >> 2);
                const float sx0 = sxs[lm * 32 + g];
                const float sx1 = sxs[(lm + 8) * 32 + g];
#pragma unroll
                for (int ni = 0; ni < 4; ++ni) {
                    const int ln = warp_n * 32 + ni * 8 + (lane & 3) * 2;
                    const float s0 = ssc[g * 128 + ln];
                    const float s1 = ssc[g * 128 + ln + 1];
                    int* h = acch[mi][ni]; int* l = accl[mi][ni]; float* f = accf[mi][ni];
                    f[0] += (float)(h[0] * 254 + l[0]) * (sx0 * s0);
                    f[1] += (float)(h[1] * 254 + l[1]) * (sx0 * s1);
                    f[2] += (float)(h[2] * 254 + l[2]) * (sx1 * s0);
                    f[3] += (float)(h[3] * 254 + l[3]) * (sx1 * s1);
                    h[0] = h[1] = h[2] = h[3] = 0;
                    l[0] = l[1] = l[2] = l[3] = 0;
                }
            }
        }
    }
    asm volatile("cp.async.wait_group 0;" ::: "memory");

    // epilogue: bias + store
#pragma unroll
    for (int mi = 0; mi < 2; ++mi) {
        const int mr0 = m0 + warp_m * 32 + mi * 16 + (lane >> 2);
#pragma unroll
        for (int ni = 0; ni < 4; ++ni) {
            const int col = n0 + warp_n * 32 + ni * 8 + (lane & 3) * 2;
            const float b0 = bias[col], b1 = bias[col + 1];
            const float* f = accf[mi][ni];
            float2 v0 = { f[0] + b0, f[1] + b1 };
            float2 v1 = { f[2] + b0, f[3] + b1 };
            *reinterpret_cast<float2*>(out + (size_t)mr0 * NDIM + col)       = v0;
            *reinterpret_cast<float2*>(out + (size_t)(mr0 + 8) * NDIM + col) = v1;
        }
    }
}

// ---------------- Launch ----------------
extern "C" void kernel_launch(void* const* d_in, const int* in_sizes, int n_in,
                              void* d_out, int out_size) {
    const float* x       = (const float*)d_in[0];
    const int*   qweight = (const int*)d_in[1];
    const float* scales  = (const float*)d_in[2];
    const int*   qzeros  = (const int*)d_in[3];
    const float* bias    = (const float*)d_in[4];
    float* out = (float*)d_out;

    const long long xsz = (long long)in_sizes[0];
    const int M = (int)(xsz / KDIM);          // 8192

    // 1) quantize x (two-level int8)
    quant_x_kernel<<<(unsigned)(((long long)M * NGRP + 7) / 8), 256>>>(x, M);

    // 2) W -> int8 (q - z), transposed
    dequant_w_kernel<<<dim3(NDIM / 64, KDIM / 64), 256>>>(qweight, qzeros);

    // 3) int8 GEMM
    cudaFuncSetAttribute(gemm_s8_kernel, cudaFuncAttributeMaxDynamicSharedMemorySize, SMEM_TOTAL);
    gemm_s8_kernel<<<dim3(NDIM / 128, M / 64), 256, SMEM_TOTAL>>>(scales, bias, out);
}

// round 5
// speedup vs baseline: 1.1499x; 1.1499x over previous
#include <cuda_runtime.h>
#include <cuda_fp16.h>
#include <cstdint>
#include <cstddef>

#define KDIM 4096
#define NDIM 11008
#define MMAX 8192
#define BM 128
#define BN 128
#define BK 32
#define STAGES 4
#define ROWH (BK + 8)                 // padded SMEM row (40 halfs)
#define TILE_B (128 * ROWH * 2)       // 10240 B per tile (A or B)

// Static device scratch (no dynamic allocation allowed)
__device__ __half g_Xh[(size_t)MMAX * KDIM];   // x as fp16, [M, K]
__device__ __half g_Wt[(size_t)NDIM * KDIM];   // dequantized W, transposed: [N, K]

// ---------------- helpers ----------------
__device__ __forceinline__ uint32_t smem_u32(const void* p) {
    uint32_t a;
    asm("{ .reg .u64 t; cvta.to.shared.u64 t, %1; cvt.u32.u64 %0, t; }" : "=r"(a) : "l"(p));
    return a;
}

__device__ __forceinline__ void cp16(uint32_t sdst, const void* gsrc) {
    asm volatile("cp.async.cg.shared.global [%0], [%1], 16;" :: "r"(sdst), "l"(gsrc));
}

__device__ __forceinline__ void ldm_x4(uint32_t* r, uint32_t addr) {
    asm volatile("ldmatrix.sync.aligned.m8n8.x4.shared.b16 {%0,%1,%2,%3}, [%4];"
                 : "=r"(r[0]), "=r"(r[1]), "=r"(r[2]), "=r"(r[3]) : "r"(addr));
}

// fp16-accumulator MMA: D(f16) = A(f16)*B(f16) + C(f16)
__device__ __forceinline__ void mma_h(uint32_t& c0, uint32_t& c1,
                                      const uint32_t* a, uint32_t b0, uint32_t b1) {
    asm volatile("mma.sync.aligned.m16n8k16.row.col.f16.f16.f16.f16 "
                 "{%0,%1}, {%2,%3,%4,%5}, {%6,%7}, {%0,%1};"
                 : "+r"(c0), "+r"(c1)
                 : "r"(a[0]), "r"(a[1]), "r"(a[2]), "r"(a[3]), "r"(b0), "r"(b1));
}

// ---------------- Kernel 1: x fp32 -> fp16 ----------------
__global__ void convert_x_kernel(const float* __restrict__ x, long long n4) {
    long long i = (long long)blockIdx.x * blockDim.x + threadIdx.x;
    if (i < n4) {
        float4 v = reinterpret_cast<const float4*>(x)[i];
        __half2 h0 = __floats2half2_rn(v.x, v.y);
        __half2 h1 = __floats2half2_rn(v.z, v.w);
        reinterpret_cast<__half2*>(g_Xh)[i * 2]     = h0;
        reinterpret_cast<__half2*>(g_Xh)[i * 2 + 1] = h1;
    }
}

// ---------------- Kernel 2: dequant -> Wt[N][K] fp16 (SMEM transpose tile) ----------------
__global__ void __launch_bounds__(256)
dequant_kernel(const int* __restrict__ qweight,
               const float* __restrict__ scales,
               const int* __restrict__ qzeros) {
    __shared__ __half s[64][72];
    const int t  = threadIdx.x;
    const int n0 = blockIdx.x * 64;
    const int k0 = blockIdx.y * 64;
    const int g  = k0 >> 7;

    const int nl = t & 63;
    const int n  = n0 + nl;
    const uint32_t zq = ((uint32_t)qzeros[(size_t)g * (NDIM / 8) + (n >> 3)] >> ((n & 7) * 4)) & 15u;
    const float z = (float)(zq + 1u);
    const float sc = scales[(size_t)g * NDIM + n];

#pragma unroll
    for (int p = 0; p < 2; ++p) {
        const int kpl = (t >> 6) + 4 * p;
        const uint32_t qw = (uint32_t)qweight[(size_t)(k0 / 8 + kpl) * NDIM + n];
        union { uint4 u; __half h[8]; } v;
#pragma unroll
        for (int j = 0; j < 8; ++j) {
            float q = (float)((qw >> (4 * j)) & 15u);
            v.h[j] = __float2half_rn((q - z) * sc);
        }
        *reinterpret_cast<uint4*>(&s[nl][kpl * 8]) = v.u;
    }
    __syncthreads();

    const int rn = t >> 2, c = t & 3;
    uint4 v0 = *reinterpret_cast<const uint4*>(&s[rn][c * 16]);
    uint4 v1 = *reinterpret_cast<const uint4*>(&s[rn][c * 16 + 8]);
    __half* dst = &g_Wt[(size_t)(n0 + rn) * KDIM + k0 + c * 16];
    *reinterpret_cast<uint4*>(dst)     = v0;
    *reinterpret_cast<uint4*>(dst + 8) = v1;
}

// ---------------- Kernel 3: fp16-accum GEMM, fp32 promotion every 128 k ----------------
// CTA 128x128, 8 warps (2m x 4n), warp tile 64x32, BK=32, 4-stage cp.async.
__global__ void __launch_bounds__(256)
gemm_kernel(const float* __restrict__ bias, float* __restrict__ out) {
    extern __shared__ char dsm[];
    const uint32_t sbase = smem_u32(dsm);
    const uint32_t bbase = sbase + STAGES * TILE_B;

    const int tid  = threadIdx.x;
    const int lane = tid & 31;
    const int wid  = tid >> 5;
    const int warp_m = wid & 1;       // 2 -> 64 rows
    const int warp_n = wid >> 1;      // 4 -> 32 cols

    // grouped rasterization along M (B-tile reuse in L2)
    const int PN = gridDim.x, PM = gridDim.y;
    const int bid = blockIdx.y * PN + blockIdx.x;
    const int GM = 16;
    const int npg = GM * PN;
    const int fm  = (bid / npg) * GM;
    const int gsm = (PM - fm < GM) ? (PM - fm) : GM;
    const int pm  = fm + (bid % gsm);
    const int pn  = (bid % npg) / gsm;
    const int m0 = pm * BM;
    const int n0 = pn * BN;

    const __half* Ag = g_Xh + (size_t)m0 * KDIM;
    const __half* Bg = g_Wt + (size_t)n0 * KDIM;

    const int lrow = tid >> 2;        // 0..63
    const int lchk = tid & 3;

    float    accf[4][4][4];
    uint32_t hacc[4][4][2];
#pragma unroll
    for (int i = 0; i < 4; ++i)
#pragma unroll
        for (int j = 0; j < 4; ++j) {
            accf[i][j][0] = accf[i][j][1] = accf[i][j][2] = accf[i][j][3] = 0.f;
            hacc[i][j][0] = hacc[i][j][1] = 0u;
        }

    const int a_r = warp_m * 64 + (lane & 15);
    const int a_c = (lane >> 4) * 8;
    const int b_r = warp_n * 32 + ((lane >> 4) * 8) + (lane & 7);
    const int b_c = ((lane >> 3) & 1) * 8;

    const int NIT = KDIM / BK;        // 128

#pragma unroll
    for (int s = 0; s < STAGES - 1; ++s) {
        const int k0 = s * BK;
        const uint32_t sa  = sbase + s * TILE_B;
        const uint32_t sbb = bbase + s * TILE_B;
#pragma unroll
        for (int p = 0; p < 2; ++p) {
            const int row = lrow + p * 64;
            const uint32_t soff = (uint32_t)(row * ROWH + lchk * 8) * 2;
            cp16(sa  + soff, Ag + (size_t)row * KDIM + k0 + lchk * 8);
            cp16(sbb + soff, Bg + (size_t)row * KDIM + k0 + lchk * 8);
        }
        asm volatile("cp.async.commit_group;" ::: "memory");
    }

#pragma unroll 1
    for (int it = 0; it < NIT; ++it) {
        asm volatile("cp.async.wait_group 2;" ::: "memory");
        __syncthreads();

        const int nk = it + STAGES - 1;
        if (nk < NIT) {
            const int st = nk & (STAGES - 1);
            const int k0 = nk * BK;
            const uint32_t sa  = sbase + st * TILE_B;
            const uint32_t sbb = bbase + st * TILE_B;
#pragma unroll
            for (int p = 0; p < 2; ++p) {
                const int row = lrow + p * 64;
                const uint32_t soff = (uint32_t)(row * ROWH + lchk * 8) * 2;
                cp16(sa  + soff, Ag + (size_t)row * KDIM + k0 + lchk * 8);
                cp16(sbb + soff, Bg + (size_t)row * KDIM + k0 + lchk * 8);
            }
        }
        asm volatile("cp.async.commit_group;" ::: "memory");

        const int st = it & (STAGES - 1);
        const uint32_t sa  = sbase + st * TILE_B;
        const uint32_t sbb = bbase + st * TILE_B;
#pragma unroll
        for (int ks = 0; ks < 2; ++ks) {
            uint32_t Af[4][4], Bf[2][4];
#pragma unroll
            for (int mi = 0; mi < 4; ++mi)
                ldm_x4(Af[mi], sa + (uint32_t)(((a_r + mi * 16) * ROWH) + ks * 16 + a_c) * 2);
#pragma unroll
            for (int nj = 0; nj < 2; ++nj)   // each x4 covers ni = 2nj, 2nj+1
                ldm_x4(Bf[nj], sbb + (uint32_t)(((b_r + nj * 16) * ROWH) + ks * 16 + b_c) * 2);
#pragma unroll
            for (int mi = 0; mi < 4; ++mi)
#pragma unroll
                for (int nj = 0; nj < 2; ++nj) {
                    mma_h(hacc[mi][2 * nj][0],     hacc[mi][2 * nj][1],
                          Af[mi], Bf[nj][0], Bf[nj][1]);
                    mma_h(hacc[mi][2 * nj + 1][0], hacc[mi][2 * nj + 1][1],
                          Af[mi], Bf[nj][2], Bf[nj][3]);
                }
        }

        // promote fp16 chunk accumulators to fp32 every 4 iterations (128 k)
        if ((it & 3) == 3) {
#pragma unroll
            for (int mi = 0; mi < 4; ++mi)
#pragma unroll
                for (int ni = 0; ni < 4; ++ni) {
                    float2 lo = __half22float2(*reinterpret_cast<__half2*>(&hacc[mi][ni][0]));
                    float2 hi = __half22float2(*reinterpret_cast<__half2*>(&hacc[mi][ni][1]));
                    accf[mi][ni][0] += lo.x;
                    accf[mi][ni][1] += lo.y;
                    accf[mi][ni][2] += hi.x;
                    accf[mi][ni][3] += hi.y;
                    hacc[mi][ni][0] = 0u;
                    hacc[mi][ni][1] = 0u;
                }
        }
    }
    asm volatile("cp.async.wait_group 0;" ::: "memory");

    // epilogue: bias + store
    const int r  = lane >> 2;
    const int c2 = (lane & 3) * 2;
    const int orow0 = m0 + warp_m * 64;
    const int ocol0 = n0 + warp_n * 32;
#pragma unroll
    for (int ni = 0; ni < 4; ++ni) {
        const int ncol = ocol0 + ni * 8 + c2;
        const float b0 = bias[ncol], b1 = bias[ncol + 1];
#pragma unroll
        for (int mi = 0; mi < 4; ++mi) {
            const int mrow = orow0 + mi * 16 + r;
            float2 v0 = { accf[mi][ni][0] + b0, accf[mi][ni][1] + b1 };
            float2 v1 = { accf[mi][ni][2] + b0, accf[mi][ni][3] + b1 };
            *reinterpret_cast<float2*>(out + (size_t)mrow * NDIM + ncol)       = v0;
            *reinterpret_cast<float2*>(out + (size_t)(mrow + 8) * NDIM + ncol) = v1;
        }
    }
}

// ---------------- Launch ----------------
extern "C" void kernel_launch(void* const* d_in, const int* in_sizes, int n_in,
                              void* d_out, int out_size) {
    const float* x       = (const float*)d_in[0];
    const int*   qweight = (const int*)d_in[1];
    const float* scales  = (const float*)d_in[2];
    const int*   qzeros  = (const int*)d_in[3];
    const float* bias    = (const float*)d_in[4];
    float* out = (float*)d_out;

    const long long xsz = (long long)in_sizes[0];
    const int M = (int)(xsz / KDIM);          // 8192

    const long long n4 = xsz / 4;
    convert_x_kernel<<<(unsigned)((n4 + 255) / 256), 256>>>(x, n4);
    dequant_kernel<<<dim3(NDIM / 64, KDIM / 64), 256>>>(qweight, scales, qzeros);

    const int SMEM_BYTES = 2 * STAGES * TILE_B;   // 81920
    cudaFuncSetAttribute(gemm_kernel, cudaFuncAttributeMaxDynamicSharedMemorySize, SMEM_BYTES);
    gemm_kernel<<<dim3(NDIM / BN, M / BM), 256, SMEM_BYTES>>>(bias, out);
}

// round 6
// speedup vs baseline: 1.1514x; 1.0013x over previous
#include <cuda_runtime.h>
#include <cuda_fp16.h>
#include <cstdint>
#include <cstddef>

#define KDIM 4096
#define NDIM 11008
#define MMAX 8192
#define BM 128
#define BN 128
#define BK 32
#define STAGES 4
#define ROWH (BK + 8)                 // padded SMEM row (40 halfs)
#define TILE_B (128 * ROWH * 2)       // 10240 B per tile (A or B)

#define DQ_BLOCKS ((NDIM / 64) * (KDIM / 64))   // 172*64 = 11008
#define CV_THREADS_PER 8                        // floats per thread in convert part

// Static device scratch (no dynamic allocation allowed)
__device__ __half g_Xh[(size_t)MMAX * KDIM];   // x as fp16, [M, K]
__device__ __half g_Wt[(size_t)NDIM * KDIM];   // dequantized W, transposed: [N, K]

// ---------------- helpers ----------------
__device__ __forceinline__ uint32_t smem_u32(const void* p) {
    uint32_t a;
    asm("{ .reg .u64 t; cvta.to.shared.u64 t, %1; cvt.u32.u64 %0, t; }" : "=r"(a) : "l"(p));
    return a;
}

__device__ __forceinline__ void cp16(uint32_t sdst, const void* gsrc) {
    asm volatile("cp.async.cg.shared.global [%0], [%1], 16;" :: "r"(sdst), "l"(gsrc));
}

__device__ __forceinline__ void ldm_x4(uint32_t* r, uint32_t addr) {
    asm volatile("ldmatrix.sync.aligned.m8n8.x4.shared.b16 {%0,%1,%2,%3}, [%4];"
                 : "=r"(r[0]), "=r"(r[1]), "=r"(r[2]), "=r"(r[3]) : "r"(addr));
}

// fp16-accumulator MMA: D(f16) = A(f16)*B(f16) + C(f16)
__device__ __forceinline__ void mma_h(uint32_t& c0, uint32_t& c1,
                                      const uint32_t* a, uint32_t b0, uint32_t b1) {
    asm volatile("mma.sync.aligned.m16n8k16.row.col.f16.f16.f16.f16 "
                 "{%0,%1}, {%2,%3,%4,%5}, {%6,%7}, {%0,%1};"
                 : "+r"(c0), "+r"(c1)
                 : "r"(a[0]), "r"(a[1]), "r"(a[2]), "r"(a[3]), "r"(b0), "r"(b1));
}

// ---------------- Kernel 1: fused prep (dequant W  +  convert x) ----------------
// Blocks [0, DQ_BLOCKS)           : dequant 64n x 64k tile -> g_Wt
// Blocks [DQ_BLOCKS, DQ_BLOCKS+C) : convert x fp32 -> fp16, 8 floats/thread
__global__ void __launch_bounds__(256)
prep_kernel(const float* __restrict__ x, long long n8,
            const int* __restrict__ qweight,
            const float* __restrict__ scales,
            const int* __restrict__ qzeros) {
    __shared__ __half s[64][72];
    const int b = blockIdx.x;
    const int t = threadIdx.x;

    if (b < DQ_BLOCKS) {
        // ---- dequant part (identical math to round-5 dequant_kernel) ----
        const int n0 = (b % (NDIM / 64)) * 64;
        const int k0 = (b / (NDIM / 64)) * 64;
        const int g  = k0 >> 7;

        const int nl = t & 63;
        const int n  = n0 + nl;
        const uint32_t zq =
            ((uint32_t)qzeros[(size_t)g * (NDIM / 8) + (n >> 3)] >> ((n & 7) * 4)) & 15u;
        const float z  = (float)(zq + 1u);
        const float sc = scales[(size_t)g * NDIM + n];

#pragma unroll
        for (int p = 0; p < 2; ++p) {
            const int kpl = (t >> 6) + 4 * p;
            const uint32_t qw = (uint32_t)qweight[(size_t)(k0 / 8 + kpl) * NDIM + n];
            union { uint4 u; __half h[8]; } v;
#pragma unroll
            for (int j = 0; j < 8; ++j) {
                float q = (float)((qw >> (4 * j)) & 15u);
                v.h[j] = __float2half_rn((q - z) * sc);
            }
            *reinterpret_cast<uint4*>(&s[nl][kpl * 8]) = v.u;
        }
        __syncthreads();

        const int rn = t >> 2, c = t & 3;
        uint4 v0 = *reinterpret_cast<const uint4*>(&s[rn][c * 16]);
        uint4 v1 = *reinterpret_cast<const uint4*>(&s[rn][c * 16 + 8]);
        __half* dst = &g_Wt[(size_t)(n0 + rn) * KDIM + k0 + c * 16];
        *reinterpret_cast<uint4*>(dst)     = v0;
        *reinterpret_cast<uint4*>(dst + 8) = v1;
    } else {
        // ---- convert part: 8 floats (2 x float4) per thread ----
        const long long gid = (long long)(b - DQ_BLOCKS) * 256 + t;
        if (gid < n8) {
            const long long i4 = gid * 2;
            float4 v0 = reinterpret_cast<const float4*>(x)[i4];
            float4 v1 = reinterpret_cast<const float4*>(x)[i4 + 1];
            __half2* dst = reinterpret_cast<__half2*>(g_Xh) + i4 * 2;
            dst[0] = __floats2half2_rn(v0.x, v0.y);
            dst[1] = __floats2half2_rn(v0.z, v0.w);
            dst[2] = __floats2half2_rn(v1.x, v1.y);
            dst[3] = __floats2half2_rn(v1.z, v1.w);
        }
    }
}

// ---------------- Kernel 2: fp16-accum GEMM, fp32 promotion every 128 k ----------------
// CTA 128x128, 8 warps (2m x 4n), warp tile 64x32, BK=32, 4-stage cp.async.
// (byte-identical logic to round-5 gemm_kernel)
__global__ void __launch_bounds__(256)
gemm_kernel(const float* __restrict__ bias, float* __restrict__ out) {
    extern __shared__ char dsm[];
    const uint32_t sbase = smem_u32(dsm);
    const uint32_t bbase = sbase + STAGES * TILE_B;

    const int tid  = threadIdx.x;
    const int lane = tid & 31;
    const int wid  = tid >> 5;
    const int warp_m = wid & 1;       // 2 -> 64 rows
    const int warp_n = wid >> 1;      // 4 -> 32 cols

    // grouped rasterization along M (B-tile reuse in L2)
    const int PN = gridDim.x, PM = gridDim.y;
    const int bid = blockIdx.y * PN + blockIdx.x;
    const int GM = 16;
    const int npg = GM * PN;
    const int fm  = (bid / npg) * GM;
    const int gsm = (PM - fm < GM) ? (PM - fm) : GM;
    const int pm  = fm + (bid % gsm);
    const int pn  = (bid % npg) / gsm;
    const int m0 = pm * BM;
    const int n0 = pn * BN;

    const __half* Ag = g_Xh + (size_t)m0 * KDIM;
    const __half* Bg = g_Wt + (size_t)n0 * KDIM;

    const int lrow = tid >> 2;        // 0..63
    const int lchk = tid & 3;

    float    accf[4][4][4];
    uint32_t hacc[4][4][2];
#pragma unroll
    for (int i = 0; i < 4; ++i)
#pragma unroll
        for (int j = 0; j < 4; ++j) {
            accf[i][j][0] = accf[i][j][1] = accf[i][j][2] = accf[i][j][3] = 0.f;
            hacc[i][j][0] = hacc[i][j][1] = 0u;
        }

    const int a_r = warp_m * 64 + (lane & 15);
    const int a_c = (lane >> 4) * 8;
    const int b_r = warp_n * 32 + ((lane >> 4) * 8) + (lane & 7);
    const int b_c = ((lane >> 3) & 1) * 8;

    const int NIT = KDIM / BK;        // 128

#pragma unroll
    for (int s = 0; s < STAGES - 1; ++s) {
        const int k0 = s * BK;
        const uint32_t sa  = sbase + s * TILE_B;
        const uint32_t sbb = bbase + s * TILE_B;
#pragma unroll
        for (int p = 0; p < 2; ++p) {
            const int row = lrow + p * 64;
            const uint32_t soff = (uint32_t)(row * ROWH + lchk * 8) * 2;
            cp16(sa  + soff, Ag + (size_t)row * KDIM + k0 + lchk * 8);
            cp16(sbb + soff, Bg + (size_t)row * KDIM + k0 + lchk * 8);
        }
        asm volatile("cp.async.commit_group;" ::: "memory");
    }

#pragma unroll 1
    for (int it = 0; it < NIT; ++it) {
        asm volatile("cp.async.wait_group 2;" ::: "memory");
        __syncthreads();

        const int nk = it + STAGES - 1;
        if (nk < NIT) {
            const int st = nk & (STAGES - 1);
            const int k0 = nk * BK;
            const uint32_t sa  = sbase + st * TILE_B;
            const uint32_t sbb = bbase + st * TILE_B;
#pragma unroll
            for (int p = 0; p < 2; ++p) {
                const int row = lrow + p * 64;
                const uint32_t soff = (uint32_t)(row * ROWH + lchk * 8) * 2;
                cp16(sa  + soff, Ag + (size_t)row * KDIM + k0 + lchk * 8);
                cp16(sbb + soff, Bg + (size_t)row * KDIM + k0 + lchk * 8);
            }
        }
        asm volatile("cp.async.commit_group;" ::: "memory");

        const int st = it & (STAGES - 1);
        const uint32_t sa  = sbase + st * TILE_B;
        const uint32_t sbb = bbase + st * TILE_B;
#pragma unroll
        for (int ks = 0; ks < 2; ++ks) {
            uint32_t Af[4][4], Bf[2][4];
#pragma unroll
            for (int mi = 0; mi < 4; ++mi)
                ldm_x4(Af[mi], sa + (uint32_t)(((a_r + mi * 16) * ROWH) + ks * 16 + a_c) * 2);
#pragma unroll
            for (int nj = 0; nj < 2; ++nj)   // each x4 covers ni = 2nj, 2nj+1
                ldm_x4(Bf[nj], sbb + (uint32_t)(((b_r + nj * 16) * ROWH) + ks * 16 + b_c) * 2);
#pragma unroll
            for (int mi = 0; mi < 4; ++mi)
#pragma unroll
                for (int nj = 0; nj < 2; ++nj) {
                    mma_h(hacc[mi][2 * nj][0],     hacc[mi][2 * nj][1],
                          Af[mi], Bf[nj][0], Bf[nj][1]);
                    mma_h(hacc[mi][2 * nj + 1][0], hacc[mi][2 * nj + 1][1],
                          Af[mi], Bf[nj][2], Bf[nj][3]);
                }
        }

        // promote fp16 chunk accumulators to fp32 every 4 iterations (128 k)
        if ((it & 3) == 3) {
#pragma unroll
            for (int mi = 0; mi < 4; ++mi)
#pragma unroll
                for (int ni = 0; ni < 4; ++ni) {
                    float2 lo = __half22float2(*reinterpret_cast<__half2*>(&hacc[mi][ni][0]));
                    float2 hi = __half22float2(*reinterpret_cast<__half2*>(&hacc[mi][ni][1]));
                    accf[mi][ni][0] += lo.x;
                    accf[mi][ni][1] += lo.y;
                    accf[mi][ni][2] += hi.x;
                    accf[mi][ni][3] += hi.y;
                    hacc[mi][ni][0] = 0u;
                    hacc[mi][ni][1] = 0u;
                }
        }
    }
    asm volatile("cp.async.wait_group 0;" ::: "memory");

    // epilogue: bias + store
    const int r  = lane >> 2;
    const int c2 = (lane & 3) * 2;
    const int orow0 = m0 + warp_m * 64;
    const int ocol0 = n0 + warp_n * 32;
#pragma unroll
    for (int ni = 0; ni < 4; ++ni) {
        const int ncol = ocol0 + ni * 8 + c2;
        const float b0 = bias[ncol], b1 = bias[ncol + 1];
#pragma unroll
        for (int mi = 0; mi < 4; ++mi) {
            const int mrow = orow0 + mi * 16 + r;
            float2 v0 = { accf[mi][ni][0] + b0, accf[mi][ni][1] + b1 };
            float2 v1 = { accf[mi][ni][2] + b0, accf[mi][ni][3] + b1 };
            *reinterpret_cast<float2*>(out + (size_t)mrow * NDIM + ncol)       = v0;
            *reinterpret_cast<float2*>(out + (size_t)(mrow + 8) * NDIM + ncol) = v1;
        }
    }
}

// ---------------- Launch ----------------
extern "C" void kernel_launch(void* const* d_in, const int* in_sizes, int n_in,
                              void* d_out, int out_size) {
    const float* x       = (const float*)d_in[0];
    const int*   qweight = (const int*)d_in[1];
    const float* scales  = (const float*)d_in[2];
    const int*   qzeros  = (const int*)d_in[3];
    const float* bias    = (const float*)d_in[4];
    float* out = (float*)d_out;

    const long long xsz = (long long)in_sizes[0];
    const int M = (int)(xsz / KDIM);          // 8192

    // 1) fused prep: dequant W + convert x (one launch, both DRAM-bound)
    const long long n8 = xsz / 8;
    const int cv_blocks = (int)((n8 + 255) / 256);
    prep_kernel<<<DQ_BLOCKS + cv_blocks, 256>>>(x, n8, qweight, scales, qzeros);

    // 2) GEMM
    const int SMEM_BYTES = 2 * STAGES * TILE_B;   // 81920
    cudaFuncSetAttribute(gemm_kernel, cudaFuncAttributeMaxDynamicSharedMemorySize, SMEM_BYTES);
    gemm_kernel<<<dim3(NDIM / BN, M / BM), 256, SMEM_BYTES>>>(bias, out);
}

// round 7
// speedup vs baseline: 1.2345x; 1.0721x over previous
#include <cuda_runtime.h>
#include <cuda_fp16.h>
#include <cstdint>
#include <cstddef>

#define KDIM 4096
#define NDIM 11008
#define MMAX 8192
#define BM 128
#define BN 128
#define BK 64
#define ROWH (BK + 8)                 // 72 halfs = 144 B padded row
#define TILE_B (128 * ROWH * 2)       // 18432 B per tile
#define SMEM_BYTES (2 * 2 * TILE_B)   // 2 stages x (A+B) = 73728

#define DQ_BLOCKS ((NDIM / 64) * (KDIM / 64))   // 11008

// Static device scratch (no dynamic allocation allowed)
__device__ __half g_Xh[(size_t)MMAX * KDIM];   // x as fp16, [M, K]
__device__ __half g_Wt[(size_t)NDIM * KDIM];   // dequantized W, transposed: [N, K]

// ---------------- helpers ----------------
__device__ __forceinline__ uint32_t smem_u32(const void* p) {
    uint32_t a;
    asm("{ .reg .u64 t; cvta.to.shared.u64 t, %1; cvt.u32.u64 %0, t; }" : "=r"(a) : "l"(p));
    return a;
}

__device__ __forceinline__ void cp16(uint32_t sdst, const void* gsrc) {
    asm volatile("cp.async.cg.shared.global [%0], [%1], 16;" :: "r"(sdst), "l"(gsrc));
}

__device__ __forceinline__ void ldm_x4(uint32_t* r, uint32_t addr) {
    asm volatile("ldmatrix.sync.aligned.m8n8.x4.shared.b16 {%0,%1,%2,%3}, [%4];"
                 : "=r"(r[0]), "=r"(r[1]), "=r"(r[2]), "=r"(r[3]) : "r"(addr));
}

// fp16-accumulator MMA
__device__ __forceinline__ void mma_h(uint32_t& c0, uint32_t& c1,
                                      const uint32_t* a, uint32_t b0, uint32_t b1) {
    asm volatile("mma.sync.aligned.m16n8k16.row.col.f16.f16.f16.f16 "
                 "{%0,%1}, {%2,%3,%4,%5}, {%6,%7}, {%0,%1};"
                 : "+r"(c0), "+r"(c1)
                 : "r"(a[0]), "r"(a[1]), "r"(a[2]), "r"(a[3]), "r"(b0), "r"(b1));
}

// ---------------- Kernel 1: fused prep (dequant W + convert x) ----------------
__global__ void __launch_bounds__(256)
prep_kernel(const float* __restrict__ x, long long n8,
            const int* __restrict__ qweight,
            const float* __restrict__ scales,
            const int* __restrict__ qzeros) {
    __shared__ __half s[64][72];
    const int b = blockIdx.x;
    const int t = threadIdx.x;

    if (b < DQ_BLOCKS) {
        const int n0 = (b % (NDIM / 64)) * 64;
        const int k0 = (b / (NDIM / 64)) * 64;
        const int g  = k0 >> 7;

        const int nl = t & 63;
        const int n  = n0 + nl;
        const uint32_t zq =
            ((uint32_t)qzeros[(size_t)g * (NDIM / 8) + (n >> 3)] >> ((n & 7) * 4)) & 15u;
        const float z  = (float)(zq + 1u);
        const float sc = scales[(size_t)g * NDIM + n];

#pragma unroll
        for (int p = 0; p < 2; ++p) {
            const int kpl = (t >> 6) + 4 * p;
            const uint32_t qw = (uint32_t)qweight[(size_t)(k0 / 8 + kpl) * NDIM + n];
            union { uint4 u; __half h[8]; } v;
#pragma unroll
            for (int j = 0; j < 8; ++j) {
                float q = (float)((qw >> (4 * j)) & 15u);
                v.h[j] = __float2half_rn((q - z) * sc);
            }
            *reinterpret_cast<uint4*>(&s[nl][kpl * 8]) = v.u;
        }
        __syncthreads();

        const int rn = t >> 2, c = t & 3;
        uint4 v0 = *reinterpret_cast<const uint4*>(&s[rn][c * 16]);
        uint4 v1 = *reinterpret_cast<const uint4*>(&s[rn][c * 16 + 8]);
        __half* dst = &g_Wt[(size_t)(n0 + rn) * KDIM + k0 + c * 16];
        *reinterpret_cast<uint4*>(dst)     = v0;
        *reinterpret_cast<uint4*>(dst + 8) = v1;
    } else {
        const long long gid = (long long)(b - DQ_BLOCKS) * 256 + t;
        if (gid < n8) {
            const long long i4 = gid * 2;
            float4 v0 = reinterpret_cast<const float4*>(x)[i4];
            float4 v1 = reinterpret_cast<const float4*>(x)[i4 + 1];
            __half2* dst = reinterpret_cast<__half2*>(g_Xh) + i4 * 2;
            dst[0] = __floats2half2_rn(v0.x, v0.y);
            dst[1] = __floats2half2_rn(v0.z, v0.w);
            dst[2] = __floats2half2_rn(v1.x, v1.y);
            dst[3] = __floats2half2_rn(v1.z, v1.w);
        }
    }
}

// ---------------- Kernel 2: fp16-accum GEMM, BK=64, 2-stage, 1 barrier/iter ----------------
// CTA 128x128, 8 warps (2m x 4n), warp tile 64x32, fp32 promotion every 128 k.
__global__ void __launch_bounds__(256, 2)
gemm_kernel(const float* __restrict__ bias, float* __restrict__ out) {
    extern __shared__ char dsm[];
    const uint32_t sbase = smem_u32(dsm);          // A stages at 0, 1
    const uint32_t bbase = sbase + 2 * TILE_B;     // B stages at 0, 1

    const int tid  = threadIdx.x;
    const int lane = tid & 31;
    const int wid  = tid >> 5;
    const int warp_m = wid & 1;
    const int warp_n = wid >> 1;

    // grouped rasterization along M (B-tile reuse in L2)
    const int PN = gridDim.x, PM = gridDim.y;
    const int bid = blockIdx.y * PN + blockIdx.x;
    const int GM = 16;
    const int npg = GM * PN;
    const int fm  = (bid / npg) * GM;
    const int gsm = (PM - fm < GM) ? (PM - fm) : GM;
    const int pm  = fm + (bid % gsm);
    const int pn  = (bid % npg) / gsm;
    const int m0 = pm * BM;
    const int n0 = pn * BN;

    const __half* Ag = g_Xh + (size_t)m0 * KDIM;
    const __half* Bg = g_Wt + (size_t)n0 * KDIM;

    // copy indexing: 8 chunks of 16B per 128B k-row; 4 rows per thread per tile
    const int c8 = tid & 7;          // 16B chunk
    const int r0 = tid >> 3;         // 0..31

    float    accf[4][4][4];
    uint32_t hacc[4][4][2];
#pragma unroll
    for (int i = 0; i < 4; ++i)
#pragma unroll
        for (int j = 0; j < 4; ++j) {
            accf[i][j][0] = accf[i][j][1] = accf[i][j][2] = accf[i][j][3] = 0.f;
            hacc[i][j][0] = hacc[i][j][1] = 0u;
        }

    const int a_r = warp_m * 64 + (lane & 15);
    const int a_c = (lane >> 4) * 8;
    const int b_r = warp_n * 32 + ((lane >> 4) * 8) + (lane & 7);
    const int b_c = ((lane >> 3) & 1) * 8;

    const int NIT = KDIM / BK;       // 64

    // prologue: load stage 0
    {
        const uint32_t sa  = sbase;
        const uint32_t sbb = bbase;
#pragma unroll
        for (int p = 0; p < 4; ++p) {
            const int row = r0 + p * 32;
            const uint32_t soff = (uint32_t)(row * ROWH + c8 * 8) * 2;
            cp16(sa  + soff, Ag + (size_t)row * KDIM + c8 * 8);
            cp16(sbb + soff, Bg + (size_t)row * KDIM + c8 * 8);
        }
        asm volatile("cp.async.commit_group;" ::: "memory");
    }

#pragma unroll 1
    for (int it = 0; it < NIT; ++it) {
        asm volatile("cp.async.wait_group 0;" ::: "memory");
        __syncthreads();   // stage it%2 ready for all; stage (it+1)%2 free to overwrite

        if (it + 1 < NIT) {
            const int st = (it + 1) & 1;
            const int k0 = (it + 1) * BK;
            const uint32_t sa  = sbase + st * TILE_B;
            const uint32_t sbb = bbase + st * TILE_B;
#pragma unroll
            for (int p = 0; p < 4; ++p) {
                const int row = r0 + p * 32;
                const uint32_t soff = (uint32_t)(row * ROWH + c8 * 8) * 2;
                cp16(sa  + soff, Ag + (size_t)row * KDIM + k0 + c8 * 8);
                cp16(sbb + soff, Bg + (size_t)row * KDIM + k0 + c8 * 8);
            }
        }
        asm volatile("cp.async.commit_group;" ::: "memory");

        const int st = it & 1;
        const uint32_t sa  = sbase + st * TILE_B;
        const uint32_t sbb = bbase + st * TILE_B;
#pragma unroll
        for (int ks = 0; ks < 4; ++ks) {
            const int kh = ks * 16;  // k offset in halfs
            uint32_t Af[4][4], Bf[2][4];
#pragma unroll
            for (int mi = 0; mi < 4; ++mi)
                ldm_x4(Af[mi], sa + (uint32_t)(((a_r + mi * 16) * ROWH) + kh + a_c) * 2);
#pragma unroll
            for (int nj = 0; nj < 2; ++nj)
                ldm_x4(Bf[nj], sbb + (uint32_t)(((b_r + nj * 16) * ROWH) + kh + b_c) * 2);
#pragma unroll
            for (int mi = 0; mi < 4; ++mi)
#pragma unroll
                for (int nj = 0; nj < 2; ++nj) {
                    mma_h(hacc[mi][2 * nj][0],     hacc[mi][2 * nj][1],
                          Af[mi], Bf[nj][0], Bf[nj][1]);
                    mma_h(hacc[mi][2 * nj + 1][0], hacc[mi][2 * nj + 1][1],
                          Af[mi], Bf[nj][2], Bf[nj][3]);
                }
        }

        // promote fp16 chunk accumulators to fp32 every 2 iters (128 k)
        if (it & 1) {
#pragma unroll
            for (int mi = 0; mi < 4; ++mi)
#pragma unroll
                for (int ni = 0; ni < 4; ++ni) {
                    float2 lo = __half22float2(*reinterpret_cast<__half2*>(&hacc[mi][ni][0]));
                    float2 hi = __half22float2(*reinterpret_cast<__half2*>(&hacc[mi][ni][1]));
                    accf[mi][ni][0] += lo.x;
                    accf[mi][ni][1] += lo.y;
                    accf[mi][ni][2] += hi.x;
                    accf[mi][ni][3] += hi.y;
                    hacc[mi][ni][0] = 0u;
                    hacc[mi][ni][1] = 0u;
                }
        }
    }

    // epilogue: bias + store
    const int r  = lane >> 2;
    const int c2 = (lane & 3) * 2;
    const int orow0 = m0 + warp_m * 64;
    const int ocol0 = n0 + warp_n * 32;
#pragma unroll
    for (int ni = 0; ni < 4; ++ni) {
        const int ncol = ocol0 + ni * 8 + c2;
        const float b0 = bias[ncol], b1 = bias[ncol + 1];
#pragma unroll
        for (int mi = 0; mi < 4; ++mi) {
            const int mrow = orow0 + mi * 16 + r;
            float2 v0 = { accf[mi][ni][0] + b0, accf[mi][ni][1] + b1 };
            float2 v1 = { accf[mi][ni][2] + b0, accf[mi][ni][3] + b1 };
            *reinterpret_cast<float2*>(out + (size_t)mrow * NDIM + ncol)       = v0;
            *reinterpret_cast<float2*>(out + (size_t)(mrow + 8) * NDIM + ncol) = v1;
        }
    }
}

// ---------------- Launch ----------------
extern "C" void kernel_launch(void* const* d_in, const int* in_sizes, int n_in,
                              void* d_out, int out_size) {
    const float* x       = (const float*)d_in[0];
    const int*   qweight = (const int*)d_in[1];
    const float* scales  = (const float*)d_in[2];
    const int*   qzeros  = (const int*)d_in[3];
    const float* bias    = (const float*)d_in[4];
    float* out = (float*)d_out;

    const long long xsz = (long long)in_sizes[0];
    const int M = (int)(xsz / KDIM);          // 8192

    const long long n8 = xsz / 8;
    const int cv_blocks = (int)((n8 + 255) / 256);
    prep_kernel<<<DQ_BLOCKS + cv_blocks, 256>>>(x, n8, qweight, scales, qzeros);

    cudaFuncSetAttribute(gemm_kernel, cudaFuncAttributeMaxDynamicSharedMemorySize, SMEM_BYTES);
    gemm_kernel<<<dim3(NDIM / BN, M / BM), 256, SMEM_BYTES>>>(bias, out);
}